// round 1
// baseline (speedup 1.0000x reference)
#include <cuda_runtime.h>

#define B_  2
#define S_  2048
#define H_  1024
#define NH_ 16
#define DH_ 64

// Scratch for Q,K,V in [B, NH, S, DH] layout (Q pre-scaled by 1/sqrt(DH)).
__device__ float g_q[(size_t)B_ * NH_ * S_ * DH_];
__device__ float g_k[(size_t)B_ * NH_ * S_ * DH_];
__device__ float g_v[(size_t)B_ * NH_ * S_ * DH_];

// ---------------------------------------------------------------------------
// Kernel 1: QKV projection. Classic 128x128x8 register-blocked SGEMM.
// grid = (H/128, B*S/128, 3)  z selects Q/K/V. Epilogue adds bias, applies
// 1/sqrt(DH) for Q, and scatters into split-head [B,NH,S,DH] layout.
// ---------------------------------------------------------------------------
__global__ __launch_bounds__(256) void qkv_gemm(
    const float* __restrict__ hs,
    const float* __restrict__ Wq, const float* __restrict__ bq,
    const float* __restrict__ Wk, const float* __restrict__ bk,
    const float* __restrict__ Wv, const float* __restrict__ bv)
{
    __shared__ float As[8][128];   // A tile, transposed: As[k][m]
    __shared__ float Bs[8][128];   // B tile: Bs[k][n]

    const int z = blockIdx.z;
    const float* W    = (z == 0) ? Wq : (z == 1) ? Wk : Wv;
    const float* bias = (z == 0) ? bq : (z == 1) ? bk : bv;
    float* outp       = (z == 0) ? g_q : (z == 1) ? g_k : g_v;
    const float oscale = (z == 0) ? 0.125f : 1.0f;  // 1/sqrt(64)

    const int tid = threadIdx.x;
    const int m0 = blockIdx.y * 128;
    const int n0 = blockIdx.x * 128;
    const int tx = tid & 15, ty = tid >> 4;

    const int ar = tid >> 1, ac = (tid & 1) * 4;   // A tile load coords
    const int br = tid >> 5, bc = (tid & 31) * 4;  // B tile load coords

    float acc[8][8];
    #pragma unroll
    for (int i = 0; i < 8; i++)
        #pragma unroll
        for (int j = 0; j < 8; j++) acc[i][j] = 0.f;

    for (int k0 = 0; k0 < H_; k0 += 8) {
        float4 av = *reinterpret_cast<const float4*>(
            hs + (size_t)(m0 + ar) * H_ + k0 + ac);
        As[ac + 0][ar] = av.x;
        As[ac + 1][ar] = av.y;
        As[ac + 2][ar] = av.z;
        As[ac + 3][ar] = av.w;
        *reinterpret_cast<float4*>(&Bs[br][bc]) =
            *reinterpret_cast<const float4*>(W + (size_t)(k0 + br) * H_ + n0 + bc);
        __syncthreads();

        #pragma unroll
        for (int k = 0; k < 8; k++) {
            float a[8], bb[8];
            *reinterpret_cast<float4*>(a)      = *reinterpret_cast<float4*>(&As[k][ty * 8]);
            *reinterpret_cast<float4*>(a + 4)  = *reinterpret_cast<float4*>(&As[k][ty * 8 + 4]);
            *reinterpret_cast<float4*>(bb)     = *reinterpret_cast<float4*>(&Bs[k][tx * 8]);
            *reinterpret_cast<float4*>(bb + 4) = *reinterpret_cast<float4*>(&Bs[k][tx * 8 + 4]);
            #pragma unroll
            for (int i = 0; i < 8; i++)
                #pragma unroll
                for (int j = 0; j < 8; j++)
                    acc[i][j] = fmaf(a[i], bb[j], acc[i][j]);
        }
        __syncthreads();
    }

    #pragma unroll
    for (int i = 0; i < 8; i++) {
        const int m = m0 + ty * 8 + i;
        const int bidx = m >> 11;        // m / 2048
        const int s = m & (S_ - 1);
        #pragma unroll
        for (int j = 0; j < 8; j++) {
            const int n = n0 + tx * 8 + j;
            const int h = n >> 6, d = n & 63;
            const float v = (acc[i][j] + bias[n]) * oscale;
            outp[(((size_t)bidx * NH_ + h) * S_ + s) * DH_ + d] = v;
        }
    }
}

// ---------------------------------------------------------------------------
// Kernel 2: fp32 flash attention. grid = (S/64, NH, B), 256 threads.
// 64x64 Q tile per block, iterate 64-wide K/V tiles with online softmax.
// Smem exactly 48KB: Qs[64][64] + KP[64*64] (K-transposed w/ XOR swizzle,
// reused for P) + Vs[64][64]. Row reductions via shuffle (16 tx lanes per row
// group share a half-warp). Thread (tx,ty) owns rows ty*4..+3, cols tx*4..+3.
// ---------------------------------------------------------------------------
__global__ __launch_bounds__(256) void flash_attn(
    const float* __restrict__ mask, float* __restrict__ out)
{
    __shared__ float Qs[64][64];
    __shared__ float KP[64 * 64];
    __shared__ float Vs[64][64];

    const int tid = threadIdx.x;
    const int tx = tid & 15, ty = tid >> 4;
    const int qt = blockIdx.x, hh = blockIdx.y, bb = blockIdx.z;

    const size_t base = ((size_t)bb * NH_ + hh) * S_ * DH_;
    const float* Qg = g_q + base;
    const float* Kg = g_k + base;
    const float* Vg = g_v + base;

    // Load Q tile (already scaled by 1/sqrt(DH) in projection)
    #pragma unroll
    for (int t = 0; t < 4; t++) {
        const int f = t * 256 + tid;
        const int r = f >> 4, c = (f & 15) << 2;
        *reinterpret_cast<float4*>(&Qs[r][c]) =
            *reinterpret_cast<const float4*>(Qg + (size_t)(qt * 64 + r) * DH_ + c);
    }

    float m_i[4], l_i[4], acc[4][4];
    #pragma unroll
    for (int i = 0; i < 4; i++) {
        m_i[i] = -1e30f;
        l_i[i] = 0.f;
        #pragma unroll
        for (int j = 0; j < 4; j++) acc[i][j] = 0.f;
    }

    for (int kc = 0; kc < S_ / 64; kc++) {
        __syncthreads();  // previous iter's KP/Vs readers done (also covers Qs load)

        // Load K tile transposed with XOR swizzle (conflict-free stores),
        // V tile straight.
        #pragma unroll
        for (int t = 0; t < 4; t++) {
            const int f = t * 256 + tid;
            const int r = f >> 4, c = (f & 15) << 2;
            float4 kv = *reinterpret_cast<const float4*>(
                Kg + (size_t)(kc * 64 + r) * DH_ + c);
            KP[(c + 0) * 64 + (r ^ (((c + 0) >> 2) & 15))] = kv.x;
            KP[(c + 1) * 64 + (r ^ (((c + 1) >> 2) & 15))] = kv.y;
            KP[(c + 2) * 64 + (r ^ (((c + 2) >> 2) & 15))] = kv.z;
            KP[(c + 3) * 64 + (r ^ (((c + 3) >> 2) & 15))] = kv.w;
            *reinterpret_cast<float4*>(&Vs[r][c]) =
                *reinterpret_cast<const float4*>(Vg + (size_t)(kc * 64 + r) * DH_ + c);
        }
        __syncthreads();

        // S = Q K^T (scaled); KP holds K^T: element K[row][d] at KP[d*64 + (row ^ ((d>>2)&15))]
        float sv[4][4];
        #pragma unroll
        for (int i = 0; i < 4; i++)
            #pragma unroll
            for (int j = 0; j < 4; j++) sv[i][j] = 0.f;

        #pragma unroll 4
        for (int d = 0; d < 64; d++) {
            const int sw = (d >> 2) & 15;
            float aq[4], bk[4];
            #pragma unroll
            for (int i = 0; i < 4; i++) aq[i] = Qs[ty * 4 + i][d];
            #pragma unroll
            for (int j = 0; j < 4; j++) bk[j] = KP[d * 64 + ((tx * 4 + j) ^ sw)];
            #pragma unroll
            for (int i = 0; i < 4; i++)
                #pragma unroll
                for (int j = 0; j < 4; j++)
                    sv[i][j] = fmaf(aq[i], bk[j], sv[i][j]);
        }

        // Additive mask (broadcast over q rows)
        const float* mrow = mask + (size_t)bb * S_ + kc * 64 + tx * 4;
        const float mk0 = mrow[0], mk1 = mrow[1], mk2 = mrow[2], mk3 = mrow[3];
        #pragma unroll
        for (int i = 0; i < 4; i++) {
            sv[i][0] += mk0; sv[i][1] += mk1; sv[i][2] += mk2; sv[i][3] += mk3;
        }

        // Online softmax: row groups are 16 tx lanes within a half-warp.
        float p[4][4];
        #pragma unroll
        for (int i = 0; i < 4; i++) {
            float rm = fmaxf(fmaxf(sv[i][0], sv[i][1]), fmaxf(sv[i][2], sv[i][3]));
            #pragma unroll
            for (int off = 1; off < 16; off <<= 1)
                rm = fmaxf(rm, __shfl_xor_sync(0xffffffffu, rm, off));
            const float mn = fmaxf(m_i[i], rm);
            const float alpha = __expf(m_i[i] - mn);
            m_i[i] = mn;
            float rs = 0.f;
            #pragma unroll
            for (int j = 0; j < 4; j++) {
                p[i][j] = __expf(sv[i][j] - mn);
                rs += p[i][j];
            }
            #pragma unroll
            for (int off = 1; off < 16; off <<= 1)
                rs += __shfl_xor_sync(0xffffffffu, rs, off);
            l_i[i] = l_i[i] * alpha + rs;
            #pragma unroll
            for (int j = 0; j < 4; j++) acc[i][j] *= alpha;
        }

        __syncthreads();  // all K^T reads done -> safe to overwrite KP with P
        #pragma unroll
        for (int i = 0; i < 4; i++)
            #pragma unroll
            for (int j = 0; j < 4; j++)
                KP[(ty * 4 + i) * 64 + tx * 4 + j] = p[i][j];
        __syncthreads();

        // O += P @ V
        #pragma unroll 4
        for (int kk = 0; kk < 64; kk++) {
            float pa[4];
            #pragma unroll
            for (int i = 0; i < 4; i++) pa[i] = KP[(ty * 4 + i) * 64 + kk];
            const float4 vb = *reinterpret_cast<const float4*>(&Vs[kk][tx * 4]);
            #pragma unroll
            for (int i = 0; i < 4; i++) {
                acc[i][0] = fmaf(pa[i], vb.x, acc[i][0]);
                acc[i][1] = fmaf(pa[i], vb.y, acc[i][1]);
                acc[i][2] = fmaf(pa[i], vb.z, acc[i][2]);
                acc[i][3] = fmaf(pa[i], vb.w, acc[i][3]);
            }
        }
    }

    // Epilogue: normalize and write [B,S,H] merged-head output.
    #pragma unroll
    for (int i = 0; i < 4; i++) {
        const float inv = 1.f / l_i[i];
        const int s = qt * 64 + ty * 4 + i;
        float4 o;
        o.x = acc[i][0] * inv;
        o.y = acc[i][1] * inv;
        o.z = acc[i][2] * inv;
        o.w = acc[i][3] * inv;
        *reinterpret_cast<float4*>(
            out + ((size_t)bb * S_ + s) * H_ + hh * 64 + tx * 4) = o;
    }
}

extern "C" void kernel_launch(void* const* d_in, const int* in_sizes, int n_in,
                              void* d_out, int out_size)
{
    const float* hs   = (const float*)d_in[0];
    const float* mask = (const float*)d_in[1];
    const float* Wq   = (const float*)d_in[2];
    const float* bq   = (const float*)d_in[3];
    const float* Wk   = (const float*)d_in[4];
    const float* bk   = (const float*)d_in[5];
    const float* Wv   = (const float*)d_in[6];
    const float* bv   = (const float*)d_in[7];
    float* out = (float*)d_out;

    dim3 g1(H_ / 128, (B_ * S_) / 128, 3);   // (8, 32, 3)
    qkv_gemm<<<g1, 256>>>(hs, Wq, bq, Wk, bk, Wv, bv);

    dim3 g2(S_ / 64, NH_, B_);               // (32, 16, 2)
    flash_attn<<<g2, 256>>>(mask, out);
}

// round 3
// speedup vs baseline: 3.1825x; 3.1825x over previous
#include <cuda_runtime.h>

#define B_  2
#define S_  2048
#define H_  1024
#define NH_ 16
#define DH_ 64

// Scratch Q,K,V in [B, NH, S, DH] (Q pre-scaled by 1/sqrt(DH)).
__device__ float g_q[(size_t)B_ * NH_ * S_ * DH_];
__device__ float g_k[(size_t)B_ * NH_ * S_ * DH_];
__device__ float g_v[(size_t)B_ * NH_ * S_ * DH_];

__device__ __forceinline__ unsigned f2tf32(float x) {
    unsigned u;
    asm("cvt.rna.tf32.f32 %0, %1;" : "=r"(u) : "f"(x));
    return u;
}

// D += A * B  (m16n8k8, tf32 inputs, fp32 accumulate, A row-major, B col-major)
__device__ __forceinline__ void mma8(float* d, const unsigned* a, const unsigned* b) {
    asm volatile(
        "mma.sync.aligned.m16n8k8.row.col.f32.tf32.tf32.f32 "
        "{%0,%1,%2,%3}, {%4,%5,%6,%7}, {%8,%9}, {%0,%1,%2,%3};"
        : "+f"(d[0]), "+f"(d[1]), "+f"(d[2]), "+f"(d[3])
        : "r"(a[0]), "r"(a[1]), "r"(a[2]), "r"(a[3]), "r"(b[0]), "r"(b[1]));
}

// ---------------------------------------------------------------------------
// Kernel 1: QKV projection, TF32 tensor-core GEMM.
// Block tile 128m x 128n, k-chunk 32. 8 warps in 2(m) x 4(n) grid,
// warp tile 64m x 32n = 4 m16-tiles x 4 n8-tiles.
// Epilogue: +bias, Q scaled by 1/8, scatter to split-head layout.
// ---------------------------------------------------------------------------
#define AST 36    // As row stride (uints): bank-conflict-free fragment reads
#define BST 136   // Bs row stride

__global__ __launch_bounds__(256) void qkv_gemm(
    const float* __restrict__ hs,
    const float* __restrict__ Wq, const float* __restrict__ bq,
    const float* __restrict__ Wk, const float* __restrict__ bk,
    const float* __restrict__ Wv, const float* __restrict__ bv)
{
    __shared__ unsigned As[128 * AST];  // [m][k] tf32
    __shared__ unsigned Bs[32 * BST];   // [k][n] tf32

    const int z = blockIdx.z;
    const float* W    = (z == 0) ? Wq : (z == 1) ? Wk : Wv;
    const float* bias = (z == 0) ? bq : (z == 1) ? bk : bv;
    float* outp       = (z == 0) ? g_q : (z == 1) ? g_k : g_v;
    const float oscale = (z == 0) ? 0.125f : 1.0f;

    const int tid  = threadIdx.x;
    const int lane = tid & 31;
    const int wid  = tid >> 5;
    const int g = lane >> 2, j = lane & 3;
    const int wm = wid >> 2, wn = wid & 3;   // warp grid 2x4

    const int m0 = blockIdx.y * 128;
    const int n0 = blockIdx.x * 128;

    float acc[4][4][4];   // [mt][nt][reg]
    #pragma unroll
    for (int mt = 0; mt < 4; mt++)
        #pragma unroll
        for (int nt = 0; nt < 4; nt++)
            #pragma unroll
            for (int r = 0; r < 4; r++) acc[mt][nt][r] = 0.f;

    const int am  = tid >> 3, ak  = (tid & 7) * 4;    // A loader coords
    const int ldk = tid >> 5, ldn = (tid & 31) * 4;   // B loader coords

    for (int k0 = 0; k0 < H_; k0 += 32) {
        __syncthreads();
        // Load A tile 128x32 (4 passes of 32 rows)
        #pragma unroll
        for (int p = 0; p < 4; p++) {
            const int m = am + p * 32;
            float4 v = *reinterpret_cast<const float4*>(hs + (size_t)(m0 + m) * H_ + k0 + ak);
            uint4 u = { f2tf32(v.x), f2tf32(v.y), f2tf32(v.z), f2tf32(v.w) };
            *reinterpret_cast<uint4*>(&As[m * AST + ak]) = u;
        }
        // Load B tile 32x128 (4 passes of 8 rows)
        #pragma unroll
        for (int p = 0; p < 4; p++) {
            const int k = ldk + p * 8;
            float4 v = *reinterpret_cast<const float4*>(W + (size_t)(k0 + k) * H_ + n0 + ldn);
            uint4 u = { f2tf32(v.x), f2tf32(v.y), f2tf32(v.z), f2tf32(v.w) };
            *reinterpret_cast<uint4*>(&Bs[k * BST + ldn]) = u;
        }
        __syncthreads();

        #pragma unroll
        for (int kd = 0; kd < 4; kd++) {
            unsigned af[4][4];
            #pragma unroll
            for (int mt = 0; mt < 4; mt++) {
                const int row = wm * 64 + mt * 16 + g;
                const int col = kd * 8 + j;
                af[mt][0] = As[row * AST + col];
                af[mt][1] = As[(row + 8) * AST + col];
                af[mt][2] = As[row * AST + col + 4];
                af[mt][3] = As[(row + 8) * AST + col + 4];
            }
            #pragma unroll
            for (int nt = 0; nt < 4; nt++) {
                unsigned bf[2];
                const int col = wn * 32 + nt * 8 + g;
                bf[0] = Bs[(kd * 8 + j) * BST + col];
                bf[1] = Bs[(kd * 8 + j + 4) * BST + col];
                #pragma unroll
                for (int mt = 0; mt < 4; mt++)
                    mma8(acc[mt][nt], af[mt], bf);
            }
        }
    }

    // Epilogue: bias + scale, scatter to [B,NH,S,DH]
    #pragma unroll
    for (int mt = 0; mt < 4; mt++) {
        #pragma unroll
        for (int nt = 0; nt < 4; nt++) {
            const int c = n0 + wn * 32 + nt * 8 + 2 * j;
            const int h = c >> 6, d = c & 63;
            const float b0 = bias[c], b1 = bias[c + 1];
            #pragma unroll
            for (int half = 0; half < 2; half++) {
                const int m = m0 + wm * 64 + mt * 16 + g + half * 8;
                const int bb = m >> 11;
                const int s = m & (S_ - 1);
                float2 o;
                o.x = (acc[mt][nt][half * 2 + 0] + b0) * oscale;
                o.y = (acc[mt][nt][half * 2 + 1] + b1) * oscale;
                *reinterpret_cast<float2*>(
                    outp + (((size_t)bb * NH_ + h) * S_ + s) * DH_ + d) = o;
            }
        }
    }
}

// ---------------------------------------------------------------------------
// Kernel 2: TF32 flash attention. grid = (S/128, NH, B), 256 threads.
// Block: 128 q-rows; 8 warps each own one m16 tile of q-rows, full 64-wide
// kv tiles. Q fragments live in registers; K (transposed+swizzled), V, P
// staged in dynamic smem. Online softmax in registers with 4-lane shuffles.
// ---------------------------------------------------------------------------
#define KST 72    // Ks/Vs row stride
#define PST 76    // Ps row stride (also Q staging)

__global__ __launch_bounds__(256) void flash_attn(
    const float* __restrict__ mask, float* __restrict__ out)
{
    extern __shared__ unsigned smem[];
    unsigned* Ks = smem;                 // [d=64][kv=64(^swz)] tf32
    unsigned* Vs = Ks + 64 * KST;        // [kv=64][d=64] tf32
    unsigned* Ps = Vs + 64 * KST;        // [128][64] tf32 (Q staging, then P)

    const int tid  = threadIdx.x;
    const int lane = tid & 31;
    const int wid  = tid >> 5;           // 0..7, warp's m16 tile
    const int g = lane >> 2, j = lane & 3;

    const int qbase = blockIdx.x * 128;
    const int h = blockIdx.y, bb = blockIdx.z;
    const size_t base = ((size_t)bb * NH_ + h) * S_ * DH_;
    const float* Qg = g_q + base;
    const float* Kg = g_k + base;
    const float* Vg = g_v + base;
    const float* mrow = mask + (size_t)bb * S_;

    // Stage Q tile (coalesced) into Ps, then pull A-fragments into registers.
    #pragma unroll
    for (int t = 0; t < 8; t++) {
        const int f = t * 256 + tid;
        const int r = f >> 4, c = (f & 15) << 2;
        float4 v = *reinterpret_cast<const float4*>(Qg + (size_t)(qbase + r) * DH_ + c);
        uint4 u = { f2tf32(v.x), f2tf32(v.y), f2tf32(v.z), f2tf32(v.w) };
        *reinterpret_cast<uint4*>(&Ps[r * PST + c]) = u;
    }
    __syncthreads();

    unsigned Qf[8][4];
    {
        const int row = wid * 16 + g;
        #pragma unroll
        for (int kd = 0; kd < 8; kd++) {
            const int col = kd * 8 + j;
            Qf[kd][0] = Ps[row * PST + col];
            Qf[kd][1] = Ps[(row + 8) * PST + col];
            Qf[kd][2] = Ps[row * PST + col + 4];
            Qf[kd][3] = Ps[(row + 8) * PST + col + 4];
        }
    }

    float m0 = -1e30f, m1 = -1e30f, l0 = 0.f, l1 = 0.f;
    float O[8][4];
    #pragma unroll
    for (int nt = 0; nt < 8; nt++)
        #pragma unroll
        for (int r = 0; r < 4; r++) O[nt][r] = 0.f;

    for (int kc = 0; kc < S_ / 64; kc++) {
        __syncthreads();   // prior iter's Ks/Vs reads done (covers Q frag reads too)

        // Load K (transposed, XOR-swizzled) and V tiles, converting to tf32.
        #pragma unroll
        for (int t = 0; t < 4; t++) {
            const int f = t * 256 + tid;
            const int r = f >> 4, c = (f & 15) << 2;
            float4 kv4 = *reinterpret_cast<const float4*>(Kg + (size_t)(kc * 64 + r) * DH_ + c);
            Ks[(c + 0) * KST + (r ^ (((c + 0) >> 2) & 15))] = f2tf32(kv4.x);
            Ks[(c + 1) * KST + (r ^ (((c + 1) >> 2) & 15))] = f2tf32(kv4.y);
            Ks[(c + 2) * KST + (r ^ (((c + 2) >> 2) & 15))] = f2tf32(kv4.z);
            Ks[(c + 3) * KST + (r ^ (((c + 3) >> 2) & 15))] = f2tf32(kv4.w);
            float4 vv = *reinterpret_cast<const float4*>(Vg + (size_t)(kc * 64 + r) * DH_ + c);
            uint4 u = { f2tf32(vv.x), f2tf32(vv.y), f2tf32(vv.z), f2tf32(vv.w) };
            *reinterpret_cast<uint4*>(&Vs[r * KST + c]) = u;
        }
        __syncthreads();

        // S = Q @ K^T   (16 x 64 per warp)
        float Sa[8][4];
        #pragma unroll
        for (int nt = 0; nt < 8; nt++) {
            #pragma unroll
            for (int r = 0; r < 4; r++) Sa[nt][r] = 0.f;
            const int col = nt * 8 + g;
            #pragma unroll
            for (int kd = 0; kd < 8; kd++) {
                unsigned bf[2];
                bf[0] = Ks[(kd * 8 + j) * KST + (col ^ (2 * kd))];
                bf[1] = Ks[(kd * 8 + j + 4) * KST + (col ^ (2 * kd + 1))];
                mma8(Sa[nt], Qf[kd], bf);
            }
        }

        // Mask + tile max
        float tm0 = -1e30f, tm1 = -1e30f;
        #pragma unroll
        for (int nt = 0; nt < 8; nt++) {
            const float mk0 = __ldg(mrow + kc * 64 + nt * 8 + 2 * j);
            const float mk1 = __ldg(mrow + kc * 64 + nt * 8 + 2 * j + 1);
            Sa[nt][0] += mk0; Sa[nt][1] += mk1;
            Sa[nt][2] += mk0; Sa[nt][3] += mk1;
            tm0 = fmaxf(tm0, fmaxf(Sa[nt][0], Sa[nt][1]));
            tm1 = fmaxf(tm1, fmaxf(Sa[nt][2], Sa[nt][3]));
        }
        tm0 = fmaxf(tm0, __shfl_xor_sync(0xffffffffu, tm0, 1));
        tm0 = fmaxf(tm0, __shfl_xor_sync(0xffffffffu, tm0, 2));
        tm1 = fmaxf(tm1, __shfl_xor_sync(0xffffffffu, tm1, 1));
        tm1 = fmaxf(tm1, __shfl_xor_sync(0xffffffffu, tm1, 2));

        const float nm0 = fmaxf(m0, tm0), nm1 = fmaxf(m1, tm1);
        const float al0 = __expf(m0 - nm0), al1 = __expf(m1 - nm1);
        m0 = nm0; m1 = nm1;

        // P = exp(S - m), store to warp-private Ps rows as tf32
        float rs0 = 0.f, rs1 = 0.f;
        const int prow = wid * 16 + g;
        #pragma unroll
        for (int nt = 0; nt < 8; nt++) {
            const float p0 = __expf(Sa[nt][0] - nm0);
            const float p1 = __expf(Sa[nt][1] - nm0);
            const float p2 = __expf(Sa[nt][2] - nm1);
            const float p3 = __expf(Sa[nt][3] - nm1);
            rs0 += p0 + p1; rs1 += p2 + p3;
            uint2 u0 = { f2tf32(p0), f2tf32(p1) };
            uint2 u1 = { f2tf32(p2), f2tf32(p3) };
            *reinterpret_cast<uint2*>(&Ps[prow * PST + nt * 8 + 2 * j]) = u0;
            *reinterpret_cast<uint2*>(&Ps[(prow + 8) * PST + nt * 8 + 2 * j]) = u1;
        }
        rs0 += __shfl_xor_sync(0xffffffffu, rs0, 1);
        rs0 += __shfl_xor_sync(0xffffffffu, rs0, 2);
        rs1 += __shfl_xor_sync(0xffffffffu, rs1, 1);
        rs1 += __shfl_xor_sync(0xffffffffu, rs1, 2);
        l0 = l0 * al0 + rs0;
        l1 = l1 * al1 + rs1;

        #pragma unroll
        for (int nt = 0; nt < 8; nt++) {
            O[nt][0] *= al0; O[nt][1] *= al0;
            O[nt][2] *= al1; O[nt][3] *= al1;
        }
        __syncwarp();   // P stores visible within warp before fragment reads

        // O += P @ V   (P: 16 x 64 as A-frags from Ps; V: 64 x 64 B-frags)
        #pragma unroll
        for (int kk = 0; kk < 8; kk++) {
            unsigned Pf[4];
            const int col = kk * 8 + j;
            Pf[0] = Ps[prow * PST + col];
            Pf[1] = Ps[(prow + 8) * PST + col];
            Pf[2] = Ps[prow * PST + col + 4];
            Pf[3] = Ps[(prow + 8) * PST + col + 4];
            #pragma unroll
            for (int nt = 0; nt < 8; nt++) {
                unsigned bf[2];
                bf[0] = Vs[(kk * 8 + j) * KST + nt * 8 + g];
                bf[1] = Vs[(kk * 8 + j + 4) * KST + nt * 8 + g];
                mma8(O[nt], Pf, bf);
            }
        }
    }

    // Epilogue: normalize, write merged-head [B,S,H] output (float2 stores).
    const float inv0 = 1.f / l0, inv1 = 1.f / l1;
    const int r0 = qbase + wid * 16 + g;
    #pragma unroll
    for (int nt = 0; nt < 8; nt++) {
        const int c = h * 64 + nt * 8 + 2 * j;
        float2 o0, o1;
        o0.x = O[nt][0] * inv0; o0.y = O[nt][1] * inv0;
        o1.x = O[nt][2] * inv1; o1.y = O[nt][3] * inv1;
        *reinterpret_cast<float2*>(out + ((size_t)bb * S_ + r0) * H_ + c) = o0;
        *reinterpret_cast<float2*>(out + ((size_t)bb * S_ + r0 + 8) * H_ + c) = o1;
    }
}

extern "C" void kernel_launch(void* const* d_in, const int* in_sizes, int n_in,
                              void* d_out, int out_size)
{
    const float* hs   = (const float*)d_in[0];
    const float* mask = (const float*)d_in[1];
    const float* Wq   = (const float*)d_in[2];
    const float* bq   = (const float*)d_in[3];
    const float* Wk   = (const float*)d_in[4];
    const float* bk   = (const float*)d_in[5];
    const float* Wv   = (const float*)d_in[6];
    const float* bv   = (const float*)d_in[7];
    float* out = (float*)d_out;

    dim3 g1(H_ / 128, (B_ * S_) / 128, 3);   // (8, 32, 3)
    qkv_gemm<<<g1, 256>>>(hs, Wq, bq, Wk, bk, Wv, bv);

    const int smem_att = (64 * KST * 2 + 128 * PST) * 4;   // ~74 KB
    cudaFuncSetAttribute(flash_attn, cudaFuncAttributeMaxDynamicSharedMemorySize, smem_att);
    dim3 g2(S_ / 128, NH_, B_);              // (16, 16, 2)
    flash_attn<<<g2, 256, smem_att>>>(mask, out);
}

// round 4
// speedup vs baseline: 3.3763x; 1.0609x over previous
#include <cuda_runtime.h>

#define B_  2
#define S_  2048
#define H_  1024
#define NH_ 16
#define DH_ 64

// Scratch Q,K,V in [B, NH, S, DH] (Q pre-scaled by 1/sqrt(DH)).
__device__ float g_q[(size_t)B_ * NH_ * S_ * DH_];
__device__ float g_k[(size_t)B_ * NH_ * S_ * DH_];
__device__ float g_v[(size_t)B_ * NH_ * S_ * DH_];

__device__ __forceinline__ unsigned f2tf32(float x) {
    unsigned u;
    asm("cvt.rna.tf32.f32 %0, %1;" : "=r"(u) : "f"(x));
    return u;
}

// D += A * B  (m16n8k8, tf32 inputs, fp32 accumulate, A row-major, B col-major)
__device__ __forceinline__ void mma8(float* d, const unsigned* a, const unsigned* b) {
    asm volatile(
        "mma.sync.aligned.m16n8k8.row.col.f32.tf32.tf32.f32 "
        "{%0,%1,%2,%3}, {%4,%5,%6,%7}, {%8,%9}, {%0,%1,%2,%3};"
        : "+f"(d[0]), "+f"(d[1]), "+f"(d[2]), "+f"(d[3])
        : "r"(a[0]), "r"(a[1]), "r"(a[2]), "r"(a[3]), "r"(b[0]), "r"(b[1]));
}

// ---------------------------------------------------------------------------
// Kernel 1: QKV projection, TF32 GEMM, double-buffered smem + reg prefetch.
// Block tile 128m x 128n, k-chunk 32, one __syncthreads per chunk.
// ---------------------------------------------------------------------------
#define AST 36    // As row stride (uints)
#define BST 136   // Bs row stride

__global__ __launch_bounds__(256, 2) void qkv_gemm(
    const float* __restrict__ hs,
    const float* __restrict__ Wq, const float* __restrict__ bq,
    const float* __restrict__ Wk, const float* __restrict__ bk,
    const float* __restrict__ Wv, const float* __restrict__ bv)
{
    extern __shared__ unsigned gsm[];
    unsigned* Asb[2] = { gsm, gsm + 128 * AST };
    unsigned* Bsb[2] = { gsm + 2 * 128 * AST, gsm + 2 * 128 * AST + 32 * BST };

    const int z = blockIdx.z;
    const float* W    = (z == 0) ? Wq : (z == 1) ? Wk : Wv;
    const float* bias = (z == 0) ? bq : (z == 1) ? bk : bv;
    float* outp       = (z == 0) ? g_q : (z == 1) ? g_k : g_v;
    const float oscale = (z == 0) ? 0.125f : 1.0f;

    const int tid  = threadIdx.x;
    const int lane = tid & 31;
    const int wid  = tid >> 5;
    const int g = lane >> 2, j = lane & 3;
    const int wm = wid >> 2, wn = wid & 3;   // warp grid 2x4

    const int m0 = blockIdx.y * 128;
    const int n0 = blockIdx.x * 128;

    float acc[4][4][4];
    #pragma unroll
    for (int mt = 0; mt < 4; mt++)
        #pragma unroll
        for (int nt = 0; nt < 4; nt++)
            #pragma unroll
            for (int r = 0; r < 4; r++) acc[mt][nt][r] = 0.f;

    const int am  = tid >> 3, ak  = (tid & 7) * 4;    // A loader coords
    const int ldk = tid >> 5, ldn = (tid & 31) * 4;   // B loader coords

    float4 pa[4], pb[4];
    // Prologue: chunk 0 -> regs -> smem buf 0
    #pragma unroll
    for (int p = 0; p < 4; p++) {
        pa[p] = *reinterpret_cast<const float4*>(hs + (size_t)(m0 + am + p * 32) * H_ + ak);
        pb[p] = *reinterpret_cast<const float4*>(W + (size_t)(ldk + p * 8) * H_ + n0 + ldn);
    }
    #pragma unroll
    for (int p = 0; p < 4; p++) {
        uint4 ua = { f2tf32(pa[p].x), f2tf32(pa[p].y), f2tf32(pa[p].z), f2tf32(pa[p].w) };
        *reinterpret_cast<uint4*>(&Asb[0][(am + p * 32) * AST + ak]) = ua;
        uint4 ub = { f2tf32(pb[p].x), f2tf32(pb[p].y), f2tf32(pb[p].z), f2tf32(pb[p].w) };
        *reinterpret_cast<uint4*>(&Bsb[0][(ldk + p * 8) * BST + ldn]) = ub;
    }
    __syncthreads();

    #pragma unroll 2
    for (int kc = 0; kc < H_ / 32; kc++) {
        const int cur = kc & 1;
        if (kc < H_ / 32 - 1) {
            const int k0 = (kc + 1) * 32;
            #pragma unroll
            for (int p = 0; p < 4; p++) {
                pa[p] = *reinterpret_cast<const float4*>(
                    hs + (size_t)(m0 + am + p * 32) * H_ + k0 + ak);
                pb[p] = *reinterpret_cast<const float4*>(
                    W + (size_t)(k0 + ldk + p * 8) * H_ + n0 + ldn);
            }
        }

        const unsigned* As = Asb[cur];
        const unsigned* Bs = Bsb[cur];
        #pragma unroll
        for (int kd = 0; kd < 4; kd++) {
            unsigned af[4][4];
            #pragma unroll
            for (int mt = 0; mt < 4; mt++) {
                const int row = wm * 64 + mt * 16 + g;
                const int col = kd * 8 + j;
                af[mt][0] = As[row * AST + col];
                af[mt][1] = As[(row + 8) * AST + col];
                af[mt][2] = As[row * AST + col + 4];
                af[mt][3] = As[(row + 8) * AST + col + 4];
            }
            #pragma unroll
            for (int nt = 0; nt < 4; nt++) {
                unsigned bf[2];
                const int col = wn * 32 + nt * 8 + g;
                bf[0] = Bs[(kd * 8 + j) * BST + col];
                bf[1] = Bs[(kd * 8 + j + 4) * BST + col];
                #pragma unroll
                for (int mt = 0; mt < 4; mt++)
                    mma8(acc[mt][nt], af[mt], bf);
            }
        }

        if (kc < H_ / 32 - 1) {
            const int nxt = cur ^ 1;
            #pragma unroll
            for (int p = 0; p < 4; p++) {
                uint4 ua = { f2tf32(pa[p].x), f2tf32(pa[p].y), f2tf32(pa[p].z), f2tf32(pa[p].w) };
                *reinterpret_cast<uint4*>(&Asb[nxt][(am + p * 32) * AST + ak]) = ua;
                uint4 ub = { f2tf32(pb[p].x), f2tf32(pb[p].y), f2tf32(pb[p].z), f2tf32(pb[p].w) };
                *reinterpret_cast<uint4*>(&Bsb[nxt][(ldk + p * 8) * BST + ldn]) = ub;
            }
        }
        __syncthreads();
    }

    // Epilogue: bias + scale, scatter to [B,NH,S,DH]
    #pragma unroll
    for (int mt = 0; mt < 4; mt++) {
        #pragma unroll
        for (int nt = 0; nt < 4; nt++) {
            const int c = n0 + wn * 32 + nt * 8 + 2 * j;
            const int h = c >> 6, d = c & 63;
            const float b0 = bias[c], b1 = bias[c + 1];
            #pragma unroll
            for (int half = 0; half < 2; half++) {
                const int m = m0 + wm * 64 + mt * 16 + g + half * 8;
                const int bb = m >> 11;
                const int s = m & (S_ - 1);
                float2 o;
                o.x = (acc[mt][nt][half * 2 + 0] + b0) * oscale;
                o.y = (acc[mt][nt][half * 2 + 1] + b1) * oscale;
                *reinterpret_cast<float2*>(
                    outp + (((size_t)bb * NH_ + h) * S_ + s) * DH_ + d) = o;
            }
        }
    }
}

// ---------------------------------------------------------------------------
// Kernel 2: TF32 flash attention, register-slimmed for 2 CTAs/SM.
// grid = (S/128, NH, B), 256 threads. Q lives in smem (reloaded 4 regs at a
// time inside the kd loop); P overwrites Sa in place. Regs target <=128.
// ---------------------------------------------------------------------------
#define KST 72    // Ks/Vs row stride
#define QST 68    // Qs row stride (conflict-free fragment reads)
#define PST 68    // Ps row stride

__global__ __launch_bounds__(256, 2) void flash_attn(
    const float* __restrict__ mask, float* __restrict__ out)
{
    extern __shared__ unsigned smem[];
    unsigned* Ks = smem;                   // [d=64][kv=64(^swz)] tf32
    unsigned* Vs = Ks + 64 * KST;          // [kv=64][d=64] tf32
    unsigned* Qs = Vs + 64 * KST;          // [128][64] tf32
    unsigned* Ps = Qs + 128 * QST;         // [128][64] tf32

    const int tid  = threadIdx.x;
    const int lane = tid & 31;
    const int wid  = tid >> 5;             // 0..7, warp's m16 tile
    const int g = lane >> 2, j = lane & 3;

    const int qbase = blockIdx.x * 128;
    const int h = blockIdx.y, bb = blockIdx.z;
    const size_t base = ((size_t)bb * NH_ + h) * S_ * DH_;
    const float* Qg = g_q + base;
    const float* Kg = g_k + base;
    const float* Vg = g_v + base;
    const float* mrow = mask + (size_t)bb * S_;

    // Stage Q tile (coalesced) into Qs.
    #pragma unroll
    for (int t = 0; t < 8; t++) {
        const int f = t * 256 + tid;
        const int r = f >> 4, c = (f & 15) << 2;
        float4 v = *reinterpret_cast<const float4*>(Qg + (size_t)(qbase + r) * DH_ + c);
        uint4 u = { f2tf32(v.x), f2tf32(v.y), f2tf32(v.z), f2tf32(v.w) };
        *reinterpret_cast<uint4*>(&Qs[r * QST + c]) = u;
    }

    float m0 = -1e30f, m1 = -1e30f, l0 = 0.f, l1 = 0.f;
    float O[8][4];
    #pragma unroll
    for (int nt = 0; nt < 8; nt++)
        #pragma unroll
        for (int r = 0; r < 4; r++) O[nt][r] = 0.f;

    const int prow = wid * 16 + g;
    const unsigned* qrow = &Qs[prow * QST];

    for (int kc = 0; kc < S_ / 64; kc++) {
        __syncthreads();   // prior iter's Ks/Vs/Ps readers done

        // Load K (transposed, XOR-swizzled) and V tiles, converting to tf32.
        #pragma unroll
        for (int t = 0; t < 4; t++) {
            const int f = t * 256 + tid;
            const int r = f >> 4, c = (f & 15) << 2;
            float4 kv4 = *reinterpret_cast<const float4*>(Kg + (size_t)(kc * 64 + r) * DH_ + c);
            Ks[(c + 0) * KST + (r ^ (((c + 0) >> 2) & 15))] = f2tf32(kv4.x);
            Ks[(c + 1) * KST + (r ^ (((c + 1) >> 2) & 15))] = f2tf32(kv4.y);
            Ks[(c + 2) * KST + (r ^ (((c + 2) >> 2) & 15))] = f2tf32(kv4.z);
            Ks[(c + 3) * KST + (r ^ (((c + 3) >> 2) & 15))] = f2tf32(kv4.w);
            float4 vv = *reinterpret_cast<const float4*>(Vg + (size_t)(kc * 64 + r) * DH_ + c);
            uint4 u = { f2tf32(vv.x), f2tf32(vv.y), f2tf32(vv.z), f2tf32(vv.w) };
            *reinterpret_cast<uint4*>(&Vs[r * KST + c]) = u;
        }
        __syncthreads();   // also covers Qs staging on first iter

        // S = Q @ K^T  (16 x 64 per warp). kd outer so Qf is only 4 live regs.
        float Sa[8][4];
        #pragma unroll
        for (int nt = 0; nt < 8; nt++)
            #pragma unroll
            for (int r = 0; r < 4; r++) Sa[nt][r] = 0.f;

        #pragma unroll
        for (int kd = 0; kd < 8; kd++) {
            unsigned Qf[4];
            const int col = kd * 8 + j;
            Qf[0] = qrow[col];
            Qf[1] = qrow[8 * QST + col];
            Qf[2] = qrow[col + 4];
            Qf[3] = qrow[8 * QST + col + 4];
            #pragma unroll
            for (int nt = 0; nt < 8; nt++) {
                unsigned bf[2];
                const int bcol = nt * 8 + g;
                bf[0] = Ks[(kd * 8 + j) * KST + (bcol ^ (2 * kd))];
                bf[1] = Ks[(kd * 8 + j + 4) * KST + (bcol ^ (2 * kd + 1))];
                mma8(Sa[nt], Qf, bf);
            }
        }

        // Mask + tile max
        float tm0 = -1e30f, tm1 = -1e30f;
        #pragma unroll
        for (int nt = 0; nt < 8; nt++) {
            const float mk0 = __ldg(mrow + kc * 64 + nt * 8 + 2 * j);
            const float mk1 = __ldg(mrow + kc * 64 + nt * 8 + 2 * j + 1);
            Sa[nt][0] += mk0; Sa[nt][1] += mk1;
            Sa[nt][2] += mk0; Sa[nt][3] += mk1;
            tm0 = fmaxf(tm0, fmaxf(Sa[nt][0], Sa[nt][1]));
            tm1 = fmaxf(tm1, fmaxf(Sa[nt][2], Sa[nt][3]));
        }
        tm0 = fmaxf(tm0, __shfl_xor_sync(0xffffffffu, tm0, 1));
        tm0 = fmaxf(tm0, __shfl_xor_sync(0xffffffffu, tm0, 2));
        tm1 = fmaxf(tm1, __shfl_xor_sync(0xffffffffu, tm1, 1));
        tm1 = fmaxf(tm1, __shfl_xor_sync(0xffffffffu, tm1, 2));

        const float nm0 = fmaxf(m0, tm0), nm1 = fmaxf(m1, tm1);
        const float al0 = __expf(m0 - nm0), al1 = __expf(m1 - nm1);
        m0 = nm0; m1 = nm1;

        // P = exp(S - m) in place, store to warp-private Ps rows as tf32
        float rs0 = 0.f, rs1 = 0.f;
        #pragma unroll
        for (int nt = 0; nt < 8; nt++) {
            Sa[nt][0] = __expf(Sa[nt][0] - nm0);
            Sa[nt][1] = __expf(Sa[nt][1] - nm0);
            Sa[nt][2] = __expf(Sa[nt][2] - nm1);
            Sa[nt][3] = __expf(Sa[nt][3] - nm1);
            rs0 += Sa[nt][0] + Sa[nt][1];
            rs1 += Sa[nt][2] + Sa[nt][3];
            uint2 u0 = { f2tf32(Sa[nt][0]), f2tf32(Sa[nt][1]) };
            uint2 u1 = { f2tf32(Sa[nt][2]), f2tf32(Sa[nt][3]) };
            *reinterpret_cast<uint2*>(&Ps[prow * PST + nt * 8 + 2 * j]) = u0;
            *reinterpret_cast<uint2*>(&Ps[(prow + 8) * PST + nt * 8 + 2 * j]) = u1;
        }
        rs0 += __shfl_xor_sync(0xffffffffu, rs0, 1);
        rs0 += __shfl_xor_sync(0xffffffffu, rs0, 2);
        rs1 += __shfl_xor_sync(0xffffffffu, rs1, 1);
        rs1 += __shfl_xor_sync(0xffffffffu, rs1, 2);
        l0 = l0 * al0 + rs0;
        l1 = l1 * al1 + rs1;

        #pragma unroll
        for (int nt = 0; nt < 8; nt++) {
            O[nt][0] *= al0; O[nt][1] *= al0;
            O[nt][2] *= al1; O[nt][3] *= al1;
        }
        __syncwarp();   // P stores visible within warp before fragment reads

        // O += P @ V
        #pragma unroll
        for (int kk = 0; kk < 8; kk++) {
            unsigned Pf[4];
            const int col = kk * 8 + j;
            Pf[0] = Ps[prow * PST + col];
            Pf[1] = Ps[(prow + 8) * PST + col];
            Pf[2] = Ps[prow * PST + col + 4];
            Pf[3] = Ps[(prow + 8) * PST + col + 4];
            #pragma unroll
            for (int nt = 0; nt < 8; nt++) {
                unsigned bf[2];
                bf[0] = Vs[(kk * 8 + j) * KST + nt * 8 + g];
                bf[1] = Vs[(kk * 8 + j + 4) * KST + nt * 8 + g];
                mma8(O[nt], Pf, bf);
            }
        }
    }

    // Epilogue: normalize, write merged-head [B,S,H] output (float2 stores).
    const float inv0 = 1.f / l0, inv1 = 1.f / l1;
    const int r0 = qbase + prow;
    #pragma unroll
    for (int nt = 0; nt < 8; nt++) {
        const int c = h * 64 + nt * 8 + 2 * j;
        float2 o0, o1;
        o0.x = O[nt][0] * inv0; o0.y = O[nt][1] * inv0;
        o1.x = O[nt][2] * inv1; o1.y = O[nt][3] * inv1;
        *reinterpret_cast<float2*>(out + ((size_t)bb * S_ + r0) * H_ + c) = o0;
        *reinterpret_cast<float2*>(out + ((size_t)bb * S_ + r0 + 8) * H_ + c) = o1;
    }
}

extern "C" void kernel_launch(void* const* d_in, const int* in_sizes, int n_in,
                              void* d_out, int out_size)
{
    const float* hs   = (const float*)d_in[0];
    const float* mask = (const float*)d_in[1];
    const float* Wq   = (const float*)d_in[2];
    const float* bq   = (const float*)d_in[3];
    const float* Wk   = (const float*)d_in[4];
    const float* bk   = (const float*)d_in[5];
    const float* Wv   = (const float*)d_in[6];
    const float* bv   = (const float*)d_in[7];
    float* out = (float*)d_out;

    const int smem_gemm = (2 * 128 * AST + 2 * 32 * BST) * 4;   // ~70 KB
    cudaFuncSetAttribute(qkv_gemm, cudaFuncAttributeMaxDynamicSharedMemorySize, smem_gemm);
    dim3 g1(H_ / 128, (B_ * S_) / 128, 3);   // (8, 32, 3)
    qkv_gemm<<<g1, 256, smem_gemm>>>(hs, Wq, bq, Wk, bk, Wv, bv);

    const int smem_att = (64 * KST * 2 + 128 * QST + 128 * PST) * 4;   // ~104 KB
    cudaFuncSetAttribute(flash_attn, cudaFuncAttributeMaxDynamicSharedMemorySize, smem_att);
    dim3 g2(S_ / 128, NH_, B_);              // (16, 16, 2)
    flash_attn<<<g2, 256, smem_att>>>(mask, out);
}